// round 16
// baseline (speedup 1.0000x reference)
#include <cuda_runtime.h>
#include <math.h>
#include <cstdint>

// Problem constants: B=4, T=2048, C=2048, NH=16, NKV=4, HD=128

// Scratch (allocation-free rule: __device__ globals)
__device__ float g_q[(size_t)4 * 16 * 2048 * 128];   // [B,16,T,128] roped+scaled, tf32-rounded
__device__ float g_k[(size_t)4 * 4 * 2048 * 128];    // [B,4,T,128]  roped, tf32-rounded
__device__ float g_v[(size_t)4 * 4 * 2048 * 128];    // [B,4,T,128]  tf32-rounded
__device__ float g_attn[(size_t)4 * 2048 * 2048];    // [B,T,C] tf32-rounded
// tf32-rounded copies of inputs (so cp.async + implicit mma truncation is exact)
__device__ float g_xr[(size_t)4 * 2048 * 2048];
__device__ float g_wqr[(size_t)2048 * 2048];
__device__ float g_wkr[(size_t)512 * 2048];
__device__ float g_wvr[(size_t)512 * 2048];
__device__ float g_wor[(size_t)2048 * 2048];

// ===========================================================================
// Helpers (plain sm_80+ PTX -- valid for non-'a' sm_103 target)
// ===========================================================================
__device__ __forceinline__ uint32_t smem_u32(const void* p) {
    uint32_t a;
    asm("{ .reg .u64 t; cvta.to.shared.u64 t, %1; cvt.u32.u64 %0, t; }"
        : "=r"(a) : "l"(p));
    return a;
}
__device__ __forceinline__ uint32_t f2tf32(float v) {
    uint32_t r;
    asm("cvt.rna.tf32.f32 %0, %1;" : "=r"(r) : "f"(v));
    return r;
}
__device__ __forceinline__ float roundtf(float v) {
    return __uint_as_float(f2tf32(v));
}
__device__ __forceinline__ void mma_tf32_16x8x8(float* c, const uint32_t* a,
                                                const uint32_t* b) {
    asm volatile(
        "mma.sync.aligned.m16n8k8.row.col.f32.tf32.tf32.f32 "
        "{%0,%1,%2,%3}, {%4,%5,%6,%7}, {%8,%9}, {%0,%1,%2,%3};"
        : "+f"(c[0]), "+f"(c[1]), "+f"(c[2]), "+f"(c[3])
        : "r"(a[0]), "r"(a[1]), "r"(a[2]), "r"(a[3]), "r"(b[0]), "r"(b[1]));
}
// ldmatrix x4: reg j = matrix j; within a matrix, lane i <- row i/4, word i%4.
__device__ __forceinline__ void ldmatrix_x4(uint32_t& r0, uint32_t& r1,
                                            uint32_t& r2, uint32_t& r3,
                                            uint32_t addr) {
    asm volatile("ldmatrix.sync.aligned.m8n8.x4.shared.b16 {%0,%1,%2,%3}, [%4];"
                 : "=r"(r0), "=r"(r1), "=r"(r2), "=r"(r3) : "r"(addr));
}
#define CP_ASYNC16(dst, src) \
    asm volatile("cp.async.cg.shared.global [%0], [%1], 16;" :: "r"(dst), "l"(src))
#define CP_COMMIT() asm volatile("cp.async.commit_group;" ::: "memory")
#define CP_WAIT(n)  asm volatile("cp.async.wait_group %0;" :: "n"(n) : "memory")

// ===========================================================================
// Fused pre-round kernel: all 5 inputs -> tf32-rounded scratch, one launch.
// ===========================================================================
#define N4_X  4194304
#define N4_WQ 1048576
#define N4_WK 262144
#define N4_WV 262144
#define N4_WO 1048576
#define N4_TOTAL (N4_X + N4_WQ + N4_WK + N4_WV + N4_WO)

__global__ void __launch_bounds__(256)
round_all_kernel(const float4* __restrict__ x,  const float4* __restrict__ wq,
                 const float4* __restrict__ wk, const float4* __restrict__ wv,
                 const float4* __restrict__ wo)
{
    int i = blockIdx.x * blockDim.x + threadIdx.x;
    const float4* src;
    float4* dst;
    if (i < N4_X)                      { src = x + i;  dst = (float4*)g_xr + i; }
    else if ((i -= N4_X) < N4_WQ)      { src = wq + i; dst = (float4*)g_wqr + i; }
    else if ((i -= N4_WQ) < N4_WK)     { src = wk + i; dst = (float4*)g_wkr + i; }
    else if ((i -= N4_WK) < N4_WV)     { src = wv + i; dst = (float4*)g_wvr + i; }
    else if ((i -= N4_WV) < N4_WO)     { src = wo + i; dst = (float4*)g_wor + i; }
    else return;
    float4 v = *src;
    v.x = roundtf(v.x); v.y = roundtf(v.y);
    v.z = roundtf(v.z); v.w = roundtf(v.w);
    *dst = v;
}

// ===========================================================================
// tf32 GEMM mainloop (R8 config): 128x128 tile, K=2048, 256 threads (8 warps),
// warp = 64x32, BK=32, 3-stage cp.async, one barrier per chunk, ldmatrix.
// Safe for back-to-back calls in a persistent loop: leading __syncthreads()
// orders previous tile's last smem reads before this tile's stage-0/1 writes;
// cp.async groups are FIFO so wait_group counts stay correct across tiles.
// ===========================================================================
#define SAS 36
#define TILE_WORDS (128 * SAS)
#define STG 3
#define GEMM_SMEM_BYTES (STG * 2 * TILE_WORDS * 4)   // 110592
#define NCH 64
#define PERSIST_CTAS 304     // 2 CTAs/SM x 152 SMs (GB300)

struct Frag { float acc[4][4][4]; };

__device__ __forceinline__ void gemm_issue(uint32_t sbase, int stage,
                                           const float* __restrict__ Ag,
                                           const float* __restrict__ Bg, int c)
{
    const int tid = threadIdx.x;
    const uint32_t sA = sbase + stage * (2 * TILE_WORDS * 4);
    const uint32_t sB = sA + TILE_WORDS * 4;
    const float* a = Ag + c * 32;
    const float* b = Bg + c * 32;
#pragma unroll
    for (int u = 0; u < 4; u++) {
        int f = tid + u * 256;
        int row = f >> 3;
        int c4 = f & 7;
        CP_ASYNC16(sA + (row * SAS + c4 * 4) * 4, a + (size_t)row * 2048 + c4 * 4);
        CP_ASYNC16(sB + (row * SAS + c4 * 4) * 4, b + (size_t)row * 2048 + c4 * 4);
    }
}

__device__ __forceinline__ void gemm_mainloop(const float* __restrict__ Ag,
                                              const float* __restrict__ Bg,
                                              uint32_t* smem, Frag& fr)
{
    const int tid = threadIdx.x;
    const int wid = tid >> 5;
    const int lane = tid & 31;
    const int wm = wid & 1;
    const int wn = wid >> 1;
    const uint32_t sbase = smem_u32(smem);

    // ldmatrix lane constants
    const int lj = lane >> 3;           // matrix index 0..3
    const int lr = lane & 7;            // row within matrix
    const uint32_t aoffL = ((uint32_t)(((lj & 1) * 8 + lr) * SAS + (lj >> 1) * 4)) * 4;
    const uint32_t boffL = ((uint32_t)(((lj >> 1) * 8 + lr) * SAS + (lj & 1) * 4)) * 4;

#pragma unroll
    for (int mt = 0; mt < 4; mt++)
#pragma unroll
        for (int nt = 0; nt < 4; nt++)
#pragma unroll
            for (int i = 0; i < 4; i++) fr.acc[mt][nt][i] = 0.f;

    __syncthreads();   // previous tile's smem reads complete before reuse

    gemm_issue(sbase, 0, Ag, Bg, 0); CP_COMMIT();   // group: chunk 0
    gemm_issue(sbase, 1, Ag, Bg, 1); CP_COMMIT();   // group: chunk 1

    for (int c = 0; c < NCH; c++) {
        CP_WAIT(1);
        __syncthreads();
        if (c + 2 < NCH) gemm_issue(sbase, (c + 2) % STG, Ag, Bg, c + 2);
        CP_COMMIT();

        const uint32_t AsB = sbase + (c % STG) * (2 * TILE_WORDS * 4);
        const uint32_t BsB = AsB + TILE_WORDS * 4;
#pragma unroll
        for (int ks = 0; ks < 4; ks++) {
            const int kb = ks * 8;
            uint32_t afr[4][4];
            uint32_t bfr[4][2];
#pragma unroll
            for (int mt = 0; mt < 4; mt++) {
                const int R = wm * 64 + mt * 16;
                ldmatrix_x4(afr[mt][0], afr[mt][1], afr[mt][2], afr[mt][3],
                            AsB + ((uint32_t)(R * SAS + kb)) * 4 + aoffL);
            }
#pragma unroll
            for (int ntp = 0; ntp < 2; ntp++) {
                const int Ncol = wn * 32 + ntp * 16;
                uint32_t b0, b1, b2, b3;
                ldmatrix_x4(b0, b1, b2, b3,
                            BsB + ((uint32_t)(Ncol * SAS + kb)) * 4 + boffL);
                bfr[ntp * 2][0] = b0;     bfr[ntp * 2][1] = b1;
                bfr[ntp * 2 + 1][0] = b2; bfr[ntp * 2 + 1][1] = b3;
            }
#pragma unroll
            for (int mt = 0; mt < 4; mt++)
#pragma unroll
                for (int nt = 0; nt < 4; nt++)
                    mma_tf32_16x8x8(fr.acc[mt][nt], afr[mt], bfr[nt]);
        }
    }
}

// ---------------------------------------------------------------------------
// QKV projection with fused RoPE. PERSISTENT: 1536 tiles over PERSIST_CTAS
// CTAs. tile -> (bx = tile % 24, m0 = (tile/24)*128). Outputs tf32-rounded.
// ---------------------------------------------------------------------------
__global__ void __launch_bounds__(256)
qkv_gemm_mma_kernel(const float* __restrict__ rc, const float* __restrict__ rs)
{
    extern __shared__ uint32_t smem[];
    const int tid = threadIdx.x;
    const int wid = tid >> 5;
    const int lane = tid & 31;
    const int wm = wid & 1;
    const int wn = wid >> 1;
    const int gr = lane >> 2;
    const int gc = lane & 3;

    for (int tile = blockIdx.x; tile < 1536; tile += gridDim.x) {
        const int bx = tile % 24;
        const int m0 = (tile / 24) * 128;

        const float* Bg;
        if (bx < 16)      Bg = g_wqr + (size_t)bx * 128 * 2048;
        else if (bx < 20) Bg = g_wkr + (size_t)(bx - 16) * 128 * 2048;
        else              Bg = g_wvr + (size_t)(bx - 20) * 128 * 2048;

        Frag fr;
        gemm_mainloop(g_xr + (size_t)m0 * 2048, Bg, smem, fr);

        const int mode = (bx < 16) ? 0 : (bx < 20 ? 1 : 2);   // 0=Q,1=K,2=V

#pragma unroll
        for (int mt = 0; mt < 4; mt++) {
#pragma unroll
            for (int half = 0; half < 2; half++) {
                const int m = m0 + wm * 64 + mt * 16 + gr + half * 8;
                const int bb = m >> 11;
                const int t = m & 2047;
                float* base;
                if (mode == 0)      base = g_q + (((size_t)(bb * 16 + bx)) * 2048 + t) * 128;
                else if (mode == 1) base = g_k + (((size_t)(bb * 4 + bx - 16)) * 2048 + t) * 128;
                else                base = g_v + (((size_t)(bb * 4 + bx - 20)) * 2048 + t) * 128;
#pragma unroll
                for (int nt = 0; nt < 4; nt++) {
                    const int col = wn * 32 + nt * 8 + gc * 2;
                    float e = fr.acc[mt][nt][half * 2];
                    float o = fr.acc[mt][nt][half * 2 + 1];
                    if (mode < 2) {
                        const int i = col >> 1;
                        float cc = rc[t * 64 + i];
                        float ss = rs[t * 64 + i];
                        float ne = e * cc - o * ss;
                        float no = e * ss + o * cc;
                        if (mode == 0) {
                            const float sc = 0.08838834764831845f;  // 1/sqrt(128)
                            ne *= sc; no *= sc;
                        }
                        e = ne; o = no;
                    }
                    *(float2*)(base + col) = make_float2(roundtf(e), roundtf(o));
                }
            }
        }
    }
}

// ---------------------------------------------------------------------------
// Output projection: out[m,n] = sum_k g_attn[m,k] * Wo[n,k].
// GRIDDED (measured faster than persistent for this shape): grid (16, 64).
// ---------------------------------------------------------------------------
__global__ void __launch_bounds__(256)
out_gemm_mma_kernel(float* __restrict__ out)
{
    extern __shared__ uint32_t smem[];
    const int n0 = blockIdx.x * 128;
    const int m0 = blockIdx.y * 128;

    Frag fr;
    gemm_mainloop(g_attn + (size_t)m0 * 2048, g_wor + (size_t)n0 * 2048, smem, fr);

    const int tid = threadIdx.x;
    const int wid = tid >> 5;
    const int lane = tid & 31;
    const int wm = wid & 1;
    const int wn = wid >> 1;
    const int gr = lane >> 2;
    const int gc = lane & 3;

#pragma unroll
    for (int mt = 0; mt < 4; mt++) {
#pragma unroll
        for (int half = 0; half < 2; half++) {
            const int m = m0 + wm * 64 + mt * 16 + gr + half * 8;
            float* base = out + (size_t)m * 2048 + n0;
#pragma unroll
            for (int nt = 0; nt < 4; nt++) {
                const int col = wn * 32 + nt * 8 + gc * 2;
                *(float2*)(base + col) = make_float2(fr.acc[mt][nt][half * 2],
                                                     fr.acc[mt][nt][half * 2 + 1]);
            }
        }
    }
}

// ===========================================================================
// Flash attention, mma.sync tf32, 256 threads (8 warps)  [R14 config].
// BM=128, BN=64, D=128. grid (16 h, 4 b, 16 qtiles reversed).
// One barrier per tile; K frags + P frags via ldmatrix; V scalar loads.
// Warps 0-3 skip the final fully-masked half tile (bit-exact).
// SMEM: 2 stages x (Ks[64][132] + Vs[64][136]) + Ps[128][68].
// ===========================================================================
#define KP 132
#define VP 136
#define PP 68
#define FA_STAGE_WORDS (64 * KP + 64 * VP)
#define FA_SMEM_BYTES ((2 * FA_STAGE_WORDS + 128 * PP) * 4)   // 172160

__device__ __forceinline__ void fa_issue_kv(uint32_t stage_addr,
                                            const float* __restrict__ kbase,
                                            const float* __restrict__ vbase, int kt)
{
    const int tid = threadIdx.x;
    const float* kp = kbase + (size_t)kt * 64 * 128;
    const float* vp = vbase + (size_t)kt * 64 * 128;
#pragma unroll
    for (int u = 0; u < 8; u++) {
        int f = tid + u * 256;          // 0..2047 float4 slots
        int row = f >> 5;
        int c4 = f & 31;
        CP_ASYNC16(stage_addr + (row * KP + c4 * 4) * 4,
                   kp + (size_t)row * 128 + c4 * 4);
        CP_ASYNC16(stage_addr + 64 * KP * 4 + (row * VP + c4 * 4) * 4,
                   vp + (size_t)row * 128 + c4 * 4);
    }
}

__global__ void __launch_bounds__(256)
flash_attn_mma_kernel()
{
    extern __shared__ uint32_t fsm[];
    uint32_t* Ps = fsm + 2 * FA_STAGE_WORDS;   // [qrow 0..127][kv] pad PP

    const int tid = threadIdx.x;
    const int wid = tid >> 5;            // 0..7
    const int lane = tid & 31;
    const int gr = lane >> 2;
    const int gc = lane & 3;

    const int h = blockIdx.x;
    const int b = blockIdx.y;
    const int qt = (int)gridDim.z - 1 - (int)blockIdx.z;   // heavy tiles first
    const int q0 = qt * 128;
    const int kvh = h >> 2;

    const float* qbase = g_q + (((size_t)(b * 16 + h) * 2048 + q0) * 128);
    const float* kbase = g_k + ((size_t)(b * 4 + kvh) * 2048) * 128;
    const float* vbase = g_v + ((size_t)(b * 4 + kvh) * 2048) * 128;

    const int r0 = wid * 16 + gr;        // CTA-local q row

    // ldmatrix lane constants
    const int lj = lane >> 3;
    const int lr = lane & 7;
    const uint32_t koffL = ((uint32_t)(((lj >> 1) * 8 + lr) * KP + (lj & 1) * 4)) * 4; // B pat
    const uint32_t poffL = ((uint32_t)(((lj & 1) * 8 + lr) * PP + (lj >> 1) * 4)) * 4; // A pat

    // Persistent Q fragments (values already tf32-representable -> raw bits)
    uint32_t qf[16][4];
#pragma unroll
    for (int ks = 0; ks < 16; ks++) {
        const int kk = ks * 8;
        qf[ks][0] = __float_as_uint(qbase[(size_t)(r0)     * 128 + kk + gc]);
        qf[ks][1] = __float_as_uint(qbase[(size_t)(r0 + 8) * 128 + kk + gc]);
        qf[ks][2] = __float_as_uint(qbase[(size_t)(r0)     * 128 + kk + gc + 4]);
        qf[ks][3] = __float_as_uint(qbase[(size_t)(r0 + 8) * 128 + kk + gc + 4]);
    }

    float oacc[16][4];
#pragma unroll
    for (int nt = 0; nt < 16; nt++)
#pragma unroll
        for (int i = 0; i < 4; i++) oacc[nt][i] = 0.f;

    float m0v = -1e30f, m1v = -1e30f;
    float l0 = 0.f, l1 = 0.f;

    const uint32_t sb = smem_u32(fsm);
    const uint32_t PsB = sb + 2 * FA_STAGE_WORDS * 4;
    const int ntiles = 2 * qt + 2;

    fa_issue_kv(sb, kbase, vbase, 0);
    CP_COMMIT();

    for (int kt = 0; kt < ntiles; kt++) {
        CP_WAIT(0);       // tile kt complete (prefetched during previous compute)
        __syncthreads();
        if (kt + 1 < ntiles)
            fa_issue_kv(sb + ((kt + 1) & 1) * FA_STAGE_WORDS * 4, kbase, vbase, kt + 1);
        CP_COMMIT();      // always (possibly empty)

        // Final tile (cols [q0+64, q0+128)) is fully masked for warps 0-3
        // (rows [q0, q0+64)): masked path yields p=0, alpha=1, sum=0 exactly,
        // so skipping all compute is bit-identical.
        if (kt == 2 * qt + 1 && wid < 4) continue;

        const uint32_t KsB = sb + (kt & 1) * FA_STAGE_WORDS * 4;
        const uint32_t* Vs = fsm + (kt & 1) * FA_STAGE_WORDS + 64 * KP;

        // ---- S = Q K^T (16 rows x 64 cols per warp), K frags via ldmatrix ----
        float sacc[8][4];
#pragma unroll
        for (int nt = 0; nt < 8; nt++)
#pragma unroll
            for (int i = 0; i < 4; i++) sacc[nt][i] = 0.f;

#pragma unroll
        for (int ks = 0; ks < 16; ks++) {
            const int kk = ks * 8;
            uint32_t kf[4][4];
#pragma unroll
            for (int ntp = 0; ntp < 4; ntp++) {
                ldmatrix_x4(kf[ntp][0], kf[ntp][1], kf[ntp][2], kf[ntp][3],
                            KsB + ((uint32_t)(ntp * 16 * KP + kk)) * 4 + koffL);
            }
#pragma unroll
            for (int ntp = 0; ntp < 4; ntp++) {
                uint32_t bfa[2] = { kf[ntp][0], kf[ntp][1] };
                uint32_t bfb[2] = { kf[ntp][2], kf[ntp][3] };
                mma_tf32_16x8x8(sacc[ntp * 2],     qf[ks], bfa);
                mma_tf32_16x8x8(sacc[ntp * 2 + 1], qf[ks], bfb);
            }
        }

        // ---- causal mask (only last two tiles can intersect the diagonal) ----
        if (kt >= 2 * qt) {
#pragma unroll
            for (int nt = 0; nt < 8; nt++) {
#pragma unroll
                for (int i = 0; i < 4; i++) {
                    const int rowg = q0 + r0 + (i >= 2 ? 8 : 0);
                    const int colg = kt * 64 + nt * 8 + gc * 2 + (i & 1);
                    if (colg > rowg) sacc[nt][i] = -1e30f;
                }
            }
        }

        // ---- online softmax (register + quad shuffle) ----
        float mx0 = -1e30f, mx1 = -1e30f;
#pragma unroll
        for (int nt = 0; nt < 8; nt++) {
            mx0 = fmaxf(mx0, fmaxf(sacc[nt][0], sacc[nt][1]));
            mx1 = fmaxf(mx1, fmaxf(sacc[nt][2], sacc[nt][3]));
        }
        mx0 = fmaxf(mx0, __shfl_xor_sync(0xffffffffu, mx0, 1));
        mx0 = fmaxf(mx0, __shfl_xor_sync(0xffffffffu, mx0, 2));
        mx1 = fmaxf(mx1, __shfl_xor_sync(0xffffffffu, mx1, 1));
        mx1 = fmaxf(mx1, __shfl_xor_sync(0xffffffffu, mx1, 2));

        const float mn0 = fmaxf(m0v, mx0);
        const float mn1 = fmaxf(m1v, mx1);
        const float al0 = __expf(m0v - mn0);
        const float al1 = __expf(m1v - mn1);

        float sum0 = 0.f, sum1 = 0.f;
#pragma unroll
        for (int nt = 0; nt < 8; nt++) {
            float p0 = __expf(sacc[nt][0] - mn0);
            float p1 = __expf(sacc[nt][1] - mn0);
            float p2 = __expf(sacc[nt][2] - mn1);
            float p3 = __expf(sacc[nt][3] - mn1);
            sum0 += p0 + p1;
            sum1 += p2 + p3;
            const int col = nt * 8 + gc * 2;
            Ps[(r0)     * PP + col]     = f2tf32(p0);
            Ps[(r0)     * PP + col + 1] = f2tf32(p1);
            Ps[(r0 + 8) * PP + col]     = f2tf32(p2);
            Ps[(r0 + 8) * PP + col + 1] = f2tf32(p3);
        }
        sum0 += __shfl_xor_sync(0xffffffffu, sum0, 1);
        sum0 += __shfl_xor_sync(0xffffffffu, sum0, 2);
        sum1 += __shfl_xor_sync(0xffffffffu, sum1, 1);
        sum1 += __shfl_xor_sync(0xffffffffu, sum1, 2);

        l0 = l0 * al0 + sum0;
        l1 = l1 * al1 + sum1;
        m0v = mn0;
        m1v = mn1;

#pragma unroll
        for (int nt = 0; nt < 16; nt++) {
            oacc[nt][0] *= al0; oacc[nt][1] *= al0;
            oacc[nt][2] *= al1; oacc[nt][3] *= al1;
        }
        __syncwarp();   // order P stores before P loads (warp-private rows)

        // ---- O += P V (P frags via ldmatrix, V scalar loads) ----
#pragma unroll
        for (int ks2 = 0; ks2 < 8; ks2++) {
            const int kk = ks2 * 8;
            uint32_t af[4];
            ldmatrix_x4(af[0], af[1], af[2], af[3],
                        PsB + ((uint32_t)(wid * 16 * PP + kk)) * 4 + poffL);
#pragma unroll
            for (int nt = 0; nt < 16; nt++) {
                uint32_t bf[2];
                bf[0] = Vs[(kk + gc) * VP + nt * 8 + gr];
                bf[1] = Vs[(kk + gc + 4) * VP + nt * 8 + gr];
                mma_tf32_16x8x8(oacc[nt], af, bf);
            }
        }
    }

    // ---- epilogue: normalize + tf32-round + store to g_attn [B,T,C] ----
    const float inv0 = 1.f / l0;
    const float inv1 = 1.f / l1;
    const int t0 = q0 + r0;
    float* dst0 = g_attn + ((size_t)(b * 2048 + t0) * 2048) + h * 128;
    float* dst1 = g_attn + ((size_t)(b * 2048 + t0 + 8) * 2048) + h * 128;
#pragma unroll
    for (int nt = 0; nt < 16; nt++) {
        const int col = nt * 8 + gc * 2;
        *(float2*)(dst0 + col) = make_float2(roundtf(oacc[nt][0] * inv0),
                                             roundtf(oacc[nt][1] * inv0));
        *(float2*)(dst1 + col) = make_float2(roundtf(oacc[nt][2] * inv1),
                                             roundtf(oacc[nt][3] * inv1));
    }
}

// ---------------------------------------------------------------------------
extern "C" void kernel_launch(void* const* d_in, const int* in_sizes, int n_in,
                              void* d_out, int out_size)
{
    const float* x    = (const float*)d_in[0];
    const float* wq   = (const float*)d_in[1];
    const float* wk   = (const float*)d_in[2];
    const float* wv   = (const float*)d_in[3];
    const float* wo   = (const float*)d_in[4];
    const float* rc   = (const float*)d_in[5];
    const float* rs   = (const float*)d_in[6];
    float* out = (float*)d_out;

    (void)in_sizes; (void)n_in; (void)out_size;

    cudaFuncSetAttribute(qkv_gemm_mma_kernel,
                         cudaFuncAttributeMaxDynamicSharedMemorySize, GEMM_SMEM_BYTES);
    cudaFuncSetAttribute(out_gemm_mma_kernel,
                         cudaFuncAttributeMaxDynamicSharedMemorySize, GEMM_SMEM_BYTES);
    cudaFuncSetAttribute(flash_attn_mma_kernel,
                         cudaFuncAttributeMaxDynamicSharedMemorySize, FA_SMEM_BYTES);

    // 0. Pre-round all inputs to tf32-representable fp32 (one launch)
    round_all_kernel<<<(N4_TOTAL + 255) / 256, 256>>>(
        (const float4*)x, (const float4*)wq, (const float4*)wk,
        (const float4*)wv, (const float4*)wo);

    // 1. Fused QKV projection + RoPE -> g_q/g_k/g_v (persistent CTAs)
    qkv_gemm_mma_kernel<<<PERSIST_CTAS, 256, GEMM_SMEM_BYTES>>>(rc, rs);

    // 2. Causal flash attention -> g_attn (tf32-rounded), heavy CTAs first
    flash_attn_mma_kernel<<<dim3(16, 4, 16), 256, FA_SMEM_BYTES>>>();

    // 3. Output projection -> d_out (gridded)
    out_gemm_mma_kernel<<<dim3(16, 64), 256, GEMM_SMEM_BYTES>>>(out);
}

// round 17
// speedup vs baseline: 1.0042x; 1.0042x over previous
#include <cuda_runtime.h>
#include <math.h>
#include <cstdint>

// Problem constants: B=4, T=2048, C=2048, NH=16, NKV=4, HD=128

// Scratch (allocation-free rule: __device__ globals)
__device__ float g_q[(size_t)4 * 16 * 2048 * 128];   // [B,16,T,128] roped+scaled(log2e folded), tf32-rounded
__device__ float g_k[(size_t)4 * 4 * 2048 * 128];    // [B,4,T,128]  roped, tf32-rounded
__device__ float g_v[(size_t)4 * 4 * 2048 * 128];    // [B,4,T,128]  tf32-rounded
__device__ float g_attn[(size_t)4 * 2048 * 2048];    // [B,T,C] tf32-rounded
// tf32-rounded copies of inputs (so cp.async + implicit mma truncation is exact)
__device__ float g_xr[(size_t)4 * 2048 * 2048];
__device__ float g_wqr[(size_t)2048 * 2048];
__device__ float g_wkr[(size_t)512 * 2048];
__device__ float g_wvr[(size_t)512 * 2048];
__device__ float g_wor[(size_t)2048 * 2048];

// ===========================================================================
// Helpers (plain sm_80+ PTX -- valid for non-'a' sm_103 target)
// ===========================================================================
__device__ __forceinline__ uint32_t smem_u32(const void* p) {
    uint32_t a;
    asm("{ .reg .u64 t; cvta.to.shared.u64 t, %1; cvt.u32.u64 %0, t; }"
        : "=r"(a) : "l"(p));
    return a;
}
__device__ __forceinline__ uint32_t f2tf32(float v) {
    uint32_t r;
    asm("cvt.rna.tf32.f32 %0, %1;" : "=r"(r) : "f"(v));
    return r;
}
__device__ __forceinline__ float roundtf(float v) {
    return __uint_as_float(f2tf32(v));
}
__device__ __forceinline__ void mma_tf32_16x8x8(float* c, const uint32_t* a,
                                                const uint32_t* b) {
    asm volatile(
        "mma.sync.aligned.m16n8k8.row.col.f32.tf32.tf32.f32 "
        "{%0,%1,%2,%3}, {%4,%5,%6,%7}, {%8,%9}, {%0,%1,%2,%3};"
        : "+f"(c[0]), "+f"(c[1]), "+f"(c[2]), "+f"(c[3])
        : "r"(a[0]), "r"(a[1]), "r"(a[2]), "r"(a[3]), "r"(b[0]), "r"(b[1]));
}
// ldmatrix x4: reg j = matrix j; within a matrix, lane i <- row i/4, word i%4.
__device__ __forceinline__ void ldmatrix_x4(uint32_t& r0, uint32_t& r1,
                                            uint32_t& r2, uint32_t& r3,
                                            uint32_t addr) {
    asm volatile("ldmatrix.sync.aligned.m8n8.x4.shared.b16 {%0,%1,%2,%3}, [%4];"
                 : "=r"(r0), "=r"(r1), "=r"(r2), "=r"(r3) : "r"(addr));
}
#define CP_ASYNC16(dst, src) \
    asm volatile("cp.async.cg.shared.global [%0], [%1], 16;" :: "r"(dst), "l"(src))
#define CP_COMMIT() asm volatile("cp.async.commit_group;" ::: "memory")
#define CP_WAIT(n)  asm volatile("cp.async.wait_group %0;" :: "n"(n) : "memory")

// ===========================================================================
// Fused pre-round kernel: all 5 inputs -> tf32-rounded scratch, one launch.
// ===========================================================================
#define N4_X  4194304
#define N4_WQ 1048576
#define N4_WK 262144
#define N4_WV 262144
#define N4_WO 1048576
#define N4_TOTAL (N4_X + N4_WQ + N4_WK + N4_WV + N4_WO)

__global__ void __launch_bounds__(256)
round_all_kernel(const float4* __restrict__ x,  const float4* __restrict__ wq,
                 const float4* __restrict__ wk, const float4* __restrict__ wv,
                 const float4* __restrict__ wo)
{
    int i = blockIdx.x * blockDim.x + threadIdx.x;
    const float4* src;
    float4* dst;
    if (i < N4_X)                      { src = x + i;  dst = (float4*)g_xr + i; }
    else if ((i -= N4_X) < N4_WQ)      { src = wq + i; dst = (float4*)g_wqr + i; }
    else if ((i -= N4_WQ) < N4_WK)     { src = wk + i; dst = (float4*)g_wkr + i; }
    else if ((i -= N4_WK) < N4_WV)     { src = wv + i; dst = (float4*)g_wvr + i; }
    else if ((i -= N4_WV) < N4_WO)     { src = wo + i; dst = (float4*)g_wor + i; }
    else return;
    float4 v = *src;
    v.x = roundtf(v.x); v.y = roundtf(v.y);
    v.z = roundtf(v.z); v.w = roundtf(v.w);
    *dst = v;
}

// ===========================================================================
// tf32 GEMM mainloop (R8 config): 128x128 tile, K=2048, 256 threads (8 warps),
// warp = 64x32, BK=32, 3-stage cp.async, one barrier per chunk, ldmatrix.
// Safe for back-to-back calls in a persistent loop.
// ===========================================================================
#define SAS 36
#define TILE_WORDS (128 * SAS)
#define STG 3
#define GEMM_SMEM_BYTES (STG * 2 * TILE_WORDS * 4)   // 110592
#define NCH 64
#define PERSIST_CTAS 304     // 2 CTAs/SM x 152 SMs (GB300)

struct Frag { float acc[4][4][4]; };

__device__ __forceinline__ void gemm_issue(uint32_t sbase, int stage,
                                           const float* __restrict__ Ag,
                                           const float* __restrict__ Bg, int c)
{
    const int tid = threadIdx.x;
    const uint32_t sA = sbase + stage * (2 * TILE_WORDS * 4);
    const uint32_t sB = sA + TILE_WORDS * 4;
    const float* a = Ag + c * 32;
    const float* b = Bg + c * 32;
#pragma unroll
    for (int u = 0; u < 4; u++) {
        int f = tid + u * 256;
        int row = f >> 3;
        int c4 = f & 7;
        CP_ASYNC16(sA + (row * SAS + c4 * 4) * 4, a + (size_t)row * 2048 + c4 * 4);
        CP_ASYNC16(sB + (row * SAS + c4 * 4) * 4, b + (size_t)row * 2048 + c4 * 4);
    }
}

__device__ __forceinline__ void gemm_mainloop(const float* __restrict__ Ag,
                                              const float* __restrict__ Bg,
                                              uint32_t* smem, Frag& fr)
{
    const int tid = threadIdx.x;
    const int wid = tid >> 5;
    const int lane = tid & 31;
    const int wm = wid & 1;
    const int wn = wid >> 1;
    const uint32_t sbase = smem_u32(smem);

    const int lj = lane >> 3;
    const int lr = lane & 7;
    const uint32_t aoffL = ((uint32_t)(((lj & 1) * 8 + lr) * SAS + (lj >> 1) * 4)) * 4;
    const uint32_t boffL = ((uint32_t)(((lj >> 1) * 8 + lr) * SAS + (lj & 1) * 4)) * 4;

#pragma unroll
    for (int mt = 0; mt < 4; mt++)
#pragma unroll
        for (int nt = 0; nt < 4; nt++)
#pragma unroll
            for (int i = 0; i < 4; i++) fr.acc[mt][nt][i] = 0.f;

    __syncthreads();   // previous tile's smem reads complete before reuse

    gemm_issue(sbase, 0, Ag, Bg, 0); CP_COMMIT();
    gemm_issue(sbase, 1, Ag, Bg, 1); CP_COMMIT();

    for (int c = 0; c < NCH; c++) {
        CP_WAIT(1);
        __syncthreads();
        if (c + 2 < NCH) gemm_issue(sbase, (c + 2) % STG, Ag, Bg, c + 2);
        CP_COMMIT();

        const uint32_t AsB = sbase + (c % STG) * (2 * TILE_WORDS * 4);
        const uint32_t BsB = AsB + TILE_WORDS * 4;
#pragma unroll
        for (int ks = 0; ks < 4; ks++) {
            const int kb = ks * 8;
            uint32_t afr[4][4];
            uint32_t bfr[4][2];
#pragma unroll
            for (int mt = 0; mt < 4; mt++) {
                const int R = wm * 64 + mt * 16;
                ldmatrix_x4(afr[mt][0], afr[mt][1], afr[mt][2], afr[mt][3],
                            AsB + ((uint32_t)(R * SAS + kb)) * 4 + aoffL);
            }
#pragma unroll
            for (int ntp = 0; ntp < 2; ntp++) {
                const int Ncol = wn * 32 + ntp * 16;
                uint32_t b0, b1, b2, b3;
                ldmatrix_x4(b0, b1, b2, b3,
                            BsB + ((uint32_t)(Ncol * SAS + kb)) * 4 + boffL);
                bfr[ntp * 2][0] = b0;     bfr[ntp * 2][1] = b1;
                bfr[ntp * 2 + 1][0] = b2; bfr[ntp * 2 + 1][1] = b3;
            }
#pragma unroll
            for (int mt = 0; mt < 4; mt++)
#pragma unroll
                for (int nt = 0; nt < 4; nt++)
                    mma_tf32_16x8x8(fr.acc[mt][nt], afr[mt], bfr[nt]);
        }
    }
}

// ---------------------------------------------------------------------------
// QKV projection with fused RoPE. PERSISTENT: 1536 tiles over PERSIST_CTAS.
// Q scale folds 1/sqrt(128) * log2(e) so attention can use exp2f.
// ---------------------------------------------------------------------------
__global__ void __launch_bounds__(256)
qkv_gemm_mma_kernel(const float* __restrict__ rc, const float* __restrict__ rs)
{
    extern __shared__ uint32_t smem[];
    const int tid = threadIdx.x;
    const int wid = tid >> 5;
    const int lane = tid & 31;
    const int wm = wid & 1;
    const int wn = wid >> 1;
    const int gr = lane >> 2;
    const int gc = lane & 3;

    for (int tile = blockIdx.x; tile < 1536; tile += gridDim.x) {
        const int bx = tile % 24;
        const int m0 = (tile / 24) * 128;

        const float* Bg;
        if (bx < 16)      Bg = g_wqr + (size_t)bx * 128 * 2048;
        else if (bx < 20) Bg = g_wkr + (size_t)(bx - 16) * 128 * 2048;
        else              Bg = g_wvr + (size_t)(bx - 20) * 128 * 2048;

        Frag fr;
        gemm_mainloop(g_xr + (size_t)m0 * 2048, Bg, smem, fr);

        const int mode = (bx < 16) ? 0 : (bx < 20 ? 1 : 2);   // 0=Q,1=K,2=V

#pragma unroll
        for (int mt = 0; mt < 4; mt++) {
#pragma unroll
            for (int half = 0; half < 2; half++) {
                const int m = m0 + wm * 64 + mt * 16 + gr + half * 8;
                const int bb = m >> 11;
                const int t = m & 2047;
                float* base;
                if (mode == 0)      base = g_q + (((size_t)(bb * 16 + bx)) * 2048 + t) * 128;
                else if (mode == 1) base = g_k + (((size_t)(bb * 4 + bx - 16)) * 2048 + t) * 128;
                else                base = g_v + (((size_t)(bb * 4 + bx - 20)) * 2048 + t) * 128;
#pragma unroll
                for (int nt = 0; nt < 4; nt++) {
                    const int col = wn * 32 + nt * 8 + gc * 2;
                    float e = fr.acc[mt][nt][half * 2];
                    float o = fr.acc[mt][nt][half * 2 + 1];
                    if (mode < 2) {
                        const int i = col >> 1;
                        float cc = rc[t * 64 + i];
                        float ss = rs[t * 64 + i];
                        float ne = e * cc - o * ss;
                        float no = e * ss + o * cc;
                        if (mode == 0) {
                            // 1/sqrt(128) * log2(e): scores land in log2 domain
                            const float sc = 0.08838834764831845f * 1.4426950408889634f;
                            ne *= sc; no *= sc;
                        }
                        e = ne; o = no;
                    }
                    *(float2*)(base + col) = make_float2(roundtf(e), roundtf(o));
                }
            }
        }
    }
}

// ---------------------------------------------------------------------------
// Output projection: out[m,n] = sum_k g_attn[m,k] * Wo[n,k].
// PERSISTENT: 1024 tiles. tile -> (n0 = (tile%16)*128, m0 = (tile/16)*128).
// ---------------------------------------------------------------------------
__global__ void __launch_bounds__(256)
out_gemm_mma_kernel(float* __restrict__ out)
{
    extern __shared__ uint32_t smem[];
    const int tid = threadIdx.x;
    const int wid = tid >> 5;
    const int lane = tid & 31;
    const int wm = wid & 1;
    const int wn = wid >> 1;
    const int gr = lane >> 2;
    const int gc = lane & 3;

    for (int tile = blockIdx.x; tile < 1024; tile += gridDim.x) {
        const int n0 = (tile % 16) * 128;
        const int m0 = (tile / 16) * 128;

        Frag fr;
        gemm_mainloop(g_attn + (size_t)m0 * 2048, g_wor + (size_t)n0 * 2048, smem, fr);

#pragma unroll
        for (int mt = 0; mt < 4; mt++) {
#pragma unroll
            for (int half = 0; half < 2; half++) {
                const int m = m0 + wm * 64 + mt * 16 + gr + half * 8;
                float* base = out + (size_t)m * 2048 + n0;
#pragma unroll
                for (int nt = 0; nt < 4; nt++) {
                    const int col = wn * 32 + nt * 8 + gc * 2;
                    *(float2*)(base + col) = make_float2(fr.acc[mt][nt][half * 2],
                                                         fr.acc[mt][nt][half * 2 + 1]);
                }
            }
        }
    }
}

// ===========================================================================
// Flash attention, mma.sync tf32, 256 threads (8 warps).
// BM=128, BN=64, D=128. grid (16 h, 4 b, 16 qtiles reversed).
// Scores arrive in log2 domain (log2e folded into Q) -> exp2f softmax.
// Alpha-rescale of O is skipped (bit-exact) when all lanes have alpha==1.
// Warps 0-3 skip the final fully-masked half tile (bit-exact).
// SMEM: 2 stages x (Ks[64][132] + Vs[64][136]) + Ps[128][68].
// ===========================================================================
#define KP 132
#define VP 136
#define PP 68
#define FA_STAGE_WORDS (64 * KP + 64 * VP)
#define FA_SMEM_BYTES ((2 * FA_STAGE_WORDS + 128 * PP) * 4)   // 172160

__device__ __forceinline__ void fa_issue_kv(uint32_t stage_addr,
                                            const float* __restrict__ kbase,
                                            const float* __restrict__ vbase, int kt)
{
    const int tid = threadIdx.x;
    const float* kp = kbase + (size_t)kt * 64 * 128;
    const float* vp = vbase + (size_t)kt * 64 * 128;
#pragma unroll
    for (int u = 0; u < 8; u++) {
        int f = tid + u * 256;          // 0..2047 float4 slots
        int row = f >> 5;
        int c4 = f & 31;
        CP_ASYNC16(stage_addr + (row * KP + c4 * 4) * 4,
                   kp + (size_t)row * 128 + c4 * 4);
        CP_ASYNC16(stage_addr + 64 * KP * 4 + (row * VP + c4 * 4) * 4,
                   vp + (size_t)row * 128 + c4 * 4);
    }
}

__global__ void __launch_bounds__(256)
flash_attn_mma_kernel()
{
    extern __shared__ uint32_t fsm[];
    uint32_t* Ps = fsm + 2 * FA_STAGE_WORDS;   // [qrow 0..127][kv] pad PP

    const int tid = threadIdx.x;
    const int wid = tid >> 5;            // 0..7
    const int lane = tid & 31;
    const int gr = lane >> 2;
    const int gc = lane & 3;

    const int h = blockIdx.x;
    const int b = blockIdx.y;
    const int qt = (int)gridDim.z - 1 - (int)blockIdx.z;   // heavy tiles first
    const int q0 = qt * 128;
    const int kvh = h >> 2;

    const float* qbase = g_q + (((size_t)(b * 16 + h) * 2048 + q0) * 128);
    const float* kbase = g_k + ((size_t)(b * 4 + kvh) * 2048) * 128;
    const float* vbase = g_v + ((size_t)(b * 4 + kvh) * 2048) * 128;

    const int r0 = wid * 16 + gr;        // CTA-local q row

    // ldmatrix lane constants
    const int lj = lane >> 3;
    const int lr = lane & 7;
    const uint32_t koffL = ((uint32_t)(((lj >> 1) * 8 + lr) * KP + (lj & 1) * 4)) * 4; // B pat
    const uint32_t poffL = ((uint32_t)(((lj & 1) * 8 + lr) * PP + (lj >> 1) * 4)) * 4; // A pat

    // Persistent Q fragments (values already tf32-representable -> raw bits)
    uint32_t qf[16][4];
#pragma unroll
    for (int ks = 0; ks < 16; ks++) {
        const int kk = ks * 8;
        qf[ks][0] = __float_as_uint(qbase[(size_t)(r0)     * 128 + kk + gc]);
        qf[ks][1] = __float_as_uint(qbase[(size_t)(r0 + 8) * 128 + kk + gc]);
        qf[ks][2] = __float_as_uint(qbase[(size_t)(r0)     * 128 + kk + gc + 4]);
        qf[ks][3] = __float_as_uint(qbase[(size_t)(r0 + 8) * 128 + kk + gc + 4]);
    }

    float oacc[16][4];
#pragma unroll
    for (int nt = 0; nt < 16; nt++)
#pragma unroll
        for (int i = 0; i < 4; i++) oacc[nt][i] = 0.f;

    float m0v = -1e30f, m1v = -1e30f;
    float l0 = 0.f, l1 = 0.f;

    const uint32_t sb = smem_u32(fsm);
    const uint32_t PsB = sb + 2 * FA_STAGE_WORDS * 4;
    const int ntiles = 2 * qt + 2;

    fa_issue_kv(sb, kbase, vbase, 0);
    CP_COMMIT();

    for (int kt = 0; kt < ntiles; kt++) {
        CP_WAIT(0);       // tile kt complete (prefetched during previous compute)
        __syncthreads();
        if (kt + 1 < ntiles)
            fa_issue_kv(sb + ((kt + 1) & 1) * FA_STAGE_WORDS * 4, kbase, vbase, kt + 1);
        CP_COMMIT();      // always (possibly empty)

        // Final tile (cols [q0+64, q0+128)) is fully masked for warps 0-3:
        // skipping all compute is bit-identical (p=0, alpha=1, sum=0).
        if (kt == 2 * qt + 1 && wid < 4) continue;

        const uint32_t KsB = sb + (kt & 1) * FA_STAGE_WORDS * 4;
        const uint32_t* Vs = fsm + (kt & 1) * FA_STAGE_WORDS + 64 * KP;

        // ---- S = Q K^T (16 rows x 64 cols per warp), K frags via ldmatrix ----
        float sacc[8][4];
#pragma unroll
        for (int nt = 0; nt < 8; nt++)
#pragma unroll
            for (int i = 0; i < 4; i++) sacc[nt][i] = 0.f;

#pragma unroll
        for (int ks = 0; ks < 16; ks++) {
            const int kk = ks * 8;
            uint32_t kf[4][4];
#pragma unroll
            for (int ntp = 0; ntp < 4; ntp++) {
                ldmatrix_x4(kf[ntp][0], kf[ntp][1], kf[ntp][2], kf[ntp][3],
                            KsB + ((uint32_t)(ntp * 16 * KP + kk)) * 4 + koffL);
            }
#pragma unroll
            for (int ntp = 0; ntp < 4; ntp++) {
                uint32_t bfa[2] = { kf[ntp][0], kf[ntp][1] };
                uint32_t bfb[2] = { kf[ntp][2], kf[ntp][3] };
                mma_tf32_16x8x8(sacc[ntp * 2],     qf[ks], bfa);
                mma_tf32_16x8x8(sacc[ntp * 2 + 1], qf[ks], bfb);
            }
        }

        // ---- causal mask (only last two tiles can intersect the diagonal) ----
        if (kt >= 2 * qt) {
#pragma unroll
            for (int nt = 0; nt < 8; nt++) {
#pragma unroll
                for (int i = 0; i < 4; i++) {
                    const int rowg = q0 + r0 + (i >= 2 ? 8 : 0);
                    const int colg = kt * 64 + nt * 8 + gc * 2 + (i & 1);
                    if (colg > rowg) sacc[nt][i] = -1e30f;
                }
            }
        }

        // ---- online softmax in log2 domain (exp2f; quad shuffle reduce) ----
        float mx0 = -1e30f, mx1 = -1e30f;
#pragma unroll
        for (int nt = 0; nt < 8; nt++) {
            mx0 = fmaxf(mx0, fmaxf(sacc[nt][0], sacc[nt][1]));
            mx1 = fmaxf(mx1, fmaxf(sacc[nt][2], sacc[nt][3]));
        }
        mx0 = fmaxf(mx0, __shfl_xor_sync(0xffffffffu, mx0, 1));
        mx0 = fmaxf(mx0, __shfl_xor_sync(0xffffffffu, mx0, 2));
        mx1 = fmaxf(mx1, __shfl_xor_sync(0xffffffffu, mx1, 1));
        mx1 = fmaxf(mx1, __shfl_xor_sync(0xffffffffu, mx1, 2));

        const float mn0 = fmaxf(m0v, mx0);
        const float mn1 = fmaxf(m1v, mx1);
        const float al0 = exp2f(m0v - mn0);
        const float al1 = exp2f(m1v - mn1);

        float sum0 = 0.f, sum1 = 0.f;
#pragma unroll
        for (int nt = 0; nt < 8; nt++) {
            float p0 = exp2f(sacc[nt][0] - mn0);
            float p1 = exp2f(sacc[nt][1] - mn0);
            float p2 = exp2f(sacc[nt][2] - mn1);
            float p3 = exp2f(sacc[nt][3] - mn1);
            sum0 += p0 + p1;
            sum1 += p2 + p3;
            const int col = nt * 8 + gc * 2;
            Ps[(r0)     * PP + col]     = f2tf32(p0);
            Ps[(r0)     * PP + col + 1] = f2tf32(p1);
            Ps[(r0 + 8) * PP + col]     = f2tf32(p2);
            Ps[(r0 + 8) * PP + col + 1] = f2tf32(p3);
        }
        sum0 += __shfl_xor_sync(0xffffffffu, sum0, 1);
        sum0 += __shfl_xor_sync(0xffffffffu, sum0, 2);
        sum1 += __shfl_xor_sync(0xffffffffu, sum1, 1);
        sum1 += __shfl_xor_sync(0xffffffffu, sum1, 2);

        l0 = l0 * al0 + sum0;
        l1 = l1 * al1 + sum1;
        m0v = mn0;
        m1v = mn1;

        // ---- O rescale, skipped (bit-exact) when all alphas are exactly 1 ----
        const bool need = !__all_sync(0xffffffffu, (al0 == 1.0f) & (al1 == 1.0f));
        if (need) {
#pragma unroll
            for (int nt = 0; nt < 16; nt++) {
                oacc[nt][0] *= al0; oacc[nt][1] *= al0;
                oacc[nt][2] *= al1; oacc[nt][3] *= al1;
            }
        }
        __syncwarp();   // order P stores before P loads (warp-private rows)

        // ---- O += P V (P frags via ldmatrix, V scalar loads) ----
#pragma unroll
        for (int ks2 = 0; ks2 < 8; ks2++) {
            const int kk = ks2 * 8;
            uint32_t af[4];
            ldmatrix_x4(af[0], af[1], af[2], af[3],
                        PsB + ((uint32_t)(wid * 16 * PP + kk)) * 4 + poffL);
#pragma unroll
            for (int nt = 0; nt < 16; nt++) {
                uint32_t bf[2];
                bf[0] = Vs[(kk + gc) * VP + nt * 8 + gr];
                bf[1] = Vs[(kk + gc + 4) * VP + nt * 8 + gr];
                mma_tf32_16x8x8(oacc[nt], af, bf);
            }
        }
    }

    // ---- epilogue: normalize + tf32-round + store to g_attn [B,T,C] ----
    const float inv0 = 1.f / l0;
    const float inv1 = 1.f / l1;
    const int t0 = q0 + r0;
    float* dst0 = g_attn + ((size_t)(b * 2048 + t0) * 2048) + h * 128;
    float* dst1 = g_attn + ((size_t)(b * 2048 + t0 + 8) * 2048) + h * 128;
#pragma unroll
    for (int nt = 0; nt < 16; nt++) {
        const int col = nt * 8 + gc * 2;
        *(float2*)(dst0 + col) = make_float2(roundtf(oacc[nt][0] * inv0),
                                             roundtf(oacc[nt][1] * inv0));
        *(float2*)(dst1 + col) = make_float2(roundtf(oacc[nt][2] * inv1),
                                             roundtf(oacc[nt][3] * inv1));
    }
}

// ---------------------------------------------------------------------------
extern "C" void kernel_launch(void* const* d_in, const int* in_sizes, int n_in,
                              void* d_out, int out_size)
{
    const float* x    = (const float*)d_in[0];
    const float* wq   = (const float*)d_in[1];
    const float* wk   = (const float*)d_in[2];
    const float* wv   = (const float*)d_in[3];
    const float* wo   = (const float*)d_in[4];
    const float* rc   = (const float*)d_in[5];
    const float* rs   = (const float*)d_in[6];
    float* out = (float*)d_out;

    (void)in_sizes; (void)n_in; (void)out_size;

    cudaFuncSetAttribute(qkv_gemm_mma_kernel,
                         cudaFuncAttributeMaxDynamicSharedMemorySize, GEMM_SMEM_BYTES);
    cudaFuncSetAttribute(out_gemm_mma_kernel,
                         cudaFuncAttributeMaxDynamicSharedMemorySize, GEMM_SMEM_BYTES);
    cudaFuncSetAttribute(flash_attn_mma_kernel,
                         cudaFuncAttributeMaxDynamicSharedMemorySize, FA_SMEM_BYTES);

    // 0. Pre-round all inputs to tf32-representable fp32 (one launch)
    round_all_kernel<<<(N4_TOTAL + 255) / 256, 256>>>(
        (const float4*)x, (const float4*)wq, (const float4*)wk,
        (const float4*)wv, (const float4*)wo);

    // 1. Fused QKV projection + RoPE -> g_q/g_k/g_v (persistent CTAs)
    qkv_gemm_mma_kernel<<<PERSIST_CTAS, 256, GEMM_SMEM_BYTES>>>(rc, rs);

    // 2. Causal flash attention -> g_attn (tf32-rounded), heavy CTAs first
    flash_attn_mma_kernel<<<dim3(16, 4, 16), 256, FA_SMEM_BYTES>>>();

    // 3. Output projection -> d_out (persistent CTAs)
    out_gemm_mma_kernel<<<PERSIST_CTAS, 256, GEMM_SMEM_BYTES>>>(out);
}